// round 6
// baseline (speedup 1.0000x reference)
#include <cuda_runtime.h>

#define N_NODES 50000
#define N_EDGES 800000
#define IN_F 96
#define HID 64
#define N_CLS 32

// Scratch (__device__ globals, allocation-free rule)
__device__ __align__(16) float g_y[N_NODES * HID];       // x @ W1        (12.8 MB)
__device__ __align__(16) float g_agg1[N_NODES * HID];    // scatter of y  (12.8 MB)
__device__ __align__(16) float g_z[N_NODES * N_CLS];     // relu(.)@W2    ( 6.4 MB)
__device__ __align__(16) float g_agg2[N_NODES * N_CLS];  // scatter of z  ( 6.4 MB)

__device__ __forceinline__ void red_add_v4(float* p, float4 v) {
    asm volatile("red.global.add.v4.f32 [%0], {%1,%2,%3,%4};"
                 :: "l"(p), "f"(v.x), "f"(v.y), "f"(v.z), "f"(v.w) : "memory");
}

// y = x @ W1  [50000 x 64]. Register-tiled: 50 nodes/block, 160 threads,
// thread computes 5 nodes x 4 cols. Also zeroes agg1/agg2 (1200 float4/block).
__global__ void __launch_bounds__(160) gemm_x_kernel(
        const float* __restrict__ x,
        const float* __restrict__ W1,
        float* __restrict__ Y) {
    __shared__ float xs[50 * 100];    // pad stride 100 floats
    __shared__ float ws[IN_F * HID];
    int tid = threadIdx.x;

    // fold: zero accumulators. 1000 blocks x 1200 float4 = 1.2M float4 total.
    {
        const float4 zv = make_float4(0.f, 0.f, 0.f, 0.f);
        int base = blockIdx.x * 1200;
        const int n1 = N_NODES * HID / 4;   // 800000
#pragma unroll
        for (int i = tid; i < 1200; i += 160) {
            int j = base + i;
            if (j < n1) ((float4*)g_agg1)[j] = zv;
            else        ((float4*)g_agg2)[j - n1] = zv;
        }
    }

    for (int i = tid; i < IN_F * HID / 4; i += 160)
        ((float4*)ws)[i] = __ldg((const float4*)W1 + i);

    const float4* xg = (const float4*)x + blockIdx.x * 50 * (IN_F / 4);
    for (int i = tid; i < 50 * (IN_F / 4); i += 160) {
        int r = i / (IN_F / 4);
        int c = i - r * (IN_F / 4);
        *(float4*)&xs[r * 100 + c * 4] = __ldg(xg + i);
    }
    __syncthreads();

    int tx = tid & 15;   // col group: cols tx*4 .. tx*4+3
    int ty = tid >> 4;   // node group: 5 nodes each (0..9)
    float acc[5][4];
#pragma unroll
    for (int i = 0; i < 5; ++i)
#pragma unroll
        for (int j = 0; j < 4; ++j) acc[i][j] = 0.f;

    const float* xbase = &xs[ty * 5 * 100];
#pragma unroll 2
    for (int k = 0; k < IN_F; k += 4) {
        float4 wv0 = *(float4*)&ws[(k + 0) * HID + tx * 4];
        float4 wv1 = *(float4*)&ws[(k + 1) * HID + tx * 4];
        float4 wv2 = *(float4*)&ws[(k + 2) * HID + tx * 4];
        float4 wv3 = *(float4*)&ws[(k + 3) * HID + tx * 4];
#pragma unroll
        for (int i = 0; i < 5; ++i) {
            float4 xv = *(float4*)&xbase[i * 100 + k];
            acc[i][0] = fmaf(xv.x, wv0.x, acc[i][0]);
            acc[i][1] = fmaf(xv.x, wv0.y, acc[i][1]);
            acc[i][2] = fmaf(xv.x, wv0.z, acc[i][2]);
            acc[i][3] = fmaf(xv.x, wv0.w, acc[i][3]);
            acc[i][0] = fmaf(xv.y, wv1.x, acc[i][0]);
            acc[i][1] = fmaf(xv.y, wv1.y, acc[i][1]);
            acc[i][2] = fmaf(xv.y, wv1.z, acc[i][2]);
            acc[i][3] = fmaf(xv.y, wv1.w, acc[i][3]);
            acc[i][0] = fmaf(xv.z, wv2.x, acc[i][0]);
            acc[i][1] = fmaf(xv.z, wv2.y, acc[i][1]);
            acc[i][2] = fmaf(xv.z, wv2.z, acc[i][2]);
            acc[i][3] = fmaf(xv.z, wv2.w, acc[i][3]);
            acc[i][0] = fmaf(xv.w, wv3.x, acc[i][0]);
            acc[i][1] = fmaf(xv.w, wv3.y, acc[i][1]);
            acc[i][2] = fmaf(xv.w, wv3.z, acc[i][2]);
            acc[i][3] = fmaf(xv.w, wv3.w, acc[i][3]);
        }
    }
    int n0 = blockIdx.x * 50 + ty * 5;
#pragma unroll
    for (int i = 0; i < 5; ++i)
        *(float4*)&Y[(n0 + i) * HID + tx * 4] =
            make_float4(acc[i][0], acc[i][1], acc[i][2], acc[i][3]);
}

// Scatter-add: out[dst] += feat[src], C float4 chunks per edge, C = 1<<LOGC.
// Edge (src,dst) pairs loaded once per warp by 2*EPW lanes, shfl-broadcast.
template <int LOGC>
__global__ void scatter_kernel(const float4* __restrict__ feat,
                               float* __restrict__ out,
                               const int* __restrict__ src,
                               const int* __restrict__ dst) {
    const int C = 1 << LOGC;
    const int EPW = 32 >> LOGC;   // edges per warp
    int i = blockIdx.x * blockDim.x + threadIdx.x;
    int lane = threadIdx.x & 31;
    int e0 = (i - lane) >> LOGC;  // first edge of this warp
    int v = 0;
    if (lane < 2 * EPW) {
        const int* p = (lane & 1) ? dst : src;
        v = __ldg(p + e0 + (lane >> 1));
    }
    int g = lane >> LOGC;         // which edge within warp
    int s = __shfl_sync(0xffffffffu, v, 2 * g);
    int d = __shfl_sync(0xffffffffu, v, 2 * g + 1);
    int c = lane & (C - 1);
    float4 val = __ldg(feat + s * C + c);
    red_add_v4(out + d * (4 * C) + 4 * c, val);
}

// z = relu(agg1 + b1) @ W2  [50000 x 32]. 64 nodes/block, 256 threads,
// thread computes 2 nodes x 4 cols. relu+bias fused into staging.
__global__ void __launch_bounds__(256) hidden_kernel(
        const float* __restrict__ agg1,
        const float* __restrict__ b1,
        const float* __restrict__ W2,
        float* __restrict__ Z) {
    __shared__ float as[64 * 68];      // 17408 B (pad stride 68)
    __shared__ float ws[HID * N_CLS];  // 8192 B
    int tid = threadIdx.x;

    for (int i = tid; i < HID * N_CLS / 4; i += 256)
        ((float4*)ws)[i] = __ldg((const float4*)W2 + i);

    int n0 = blockIdx.x * 64;
    for (int i = tid; i < 64 * (HID / 4); i += 256) {
        int r = i >> 4;          // 16 float4 chunks per row
        int c = i & 15;
        int n = n0 + r;
        float4 v = make_float4(0.f, 0.f, 0.f, 0.f);
        if (n < N_NODES) {
            v = __ldg((const float4*)agg1 + n * (HID / 4) + c);
            float4 b = __ldg((const float4*)b1 + c);
            v.x = fmaxf(v.x + b.x, 0.f);
            v.y = fmaxf(v.y + b.y, 0.f);
            v.z = fmaxf(v.z + b.z, 0.f);
            v.w = fmaxf(v.w + b.w, 0.f);
        }
        *(float4*)&as[r * 68 + c * 4] = v;
    }
    __syncthreads();

    int tx = tid & 7;    // col group (8 x 4 cols = 32)
    int ty = tid >> 3;   // node group (0..31), 2 nodes each
    float acc[2][4];
#pragma unroll
    for (int i = 0; i < 2; ++i)
#pragma unroll
        for (int j = 0; j < 4; ++j) acc[i][j] = 0.f;

    const float* abase = &as[ty * 2 * 68];
#pragma unroll 4
    for (int k = 0; k < HID; k += 4) {
        float4 wv0 = *(float4*)&ws[(k + 0) * N_CLS + tx * 4];
        float4 wv1 = *(float4*)&ws[(k + 1) * N_CLS + tx * 4];
        float4 wv2 = *(float4*)&ws[(k + 2) * N_CLS + tx * 4];
        float4 wv3 = *(float4*)&ws[(k + 3) * N_CLS + tx * 4];
#pragma unroll
        for (int i = 0; i < 2; ++i) {
            float4 xv = *(float4*)&abase[i * 68 + k];
            acc[i][0] = fmaf(xv.x, wv0.x, acc[i][0]);
            acc[i][1] = fmaf(xv.x, wv0.y, acc[i][1]);
            acc[i][2] = fmaf(xv.x, wv0.z, acc[i][2]);
            acc[i][3] = fmaf(xv.x, wv0.w, acc[i][3]);
            acc[i][0] = fmaf(xv.y, wv1.x, acc[i][0]);
            acc[i][1] = fmaf(xv.y, wv1.y, acc[i][1]);
            acc[i][2] = fmaf(xv.y, wv1.z, acc[i][2]);
            acc[i][3] = fmaf(xv.y, wv1.w, acc[i][3]);
            acc[i][0] = fmaf(xv.z, wv2.x, acc[i][0]);
            acc[i][1] = fmaf(xv.z, wv2.y, acc[i][1]);
            acc[i][2] = fmaf(xv.z, wv2.z, acc[i][2]);
            acc[i][3] = fmaf(xv.z, wv2.w, acc[i][3]);
            acc[i][0] = fmaf(xv.w, wv3.x, acc[i][0]);
            acc[i][1] = fmaf(xv.w, wv3.y, acc[i][1]);
            acc[i][2] = fmaf(xv.w, wv3.z, acc[i][2]);
            acc[i][3] = fmaf(xv.w, wv3.w, acc[i][3]);
        }
    }
#pragma unroll
    for (int i = 0; i < 2; ++i) {
        int n = n0 + ty * 2 + i;
        if (n < N_NODES)
            *(float4*)&Z[n * N_CLS + tx * 4] =
                make_float4(acc[i][0], acc[i][1], acc[i][2], acc[i][3]);
    }
}

// out = log_softmax(agg2 + b2). One warp per node (lane = class), 8 nodes/block.
__global__ void lsm_kernel(const float* __restrict__ agg2,
                           const float* __restrict__ b2,
                           float* __restrict__ out) {
    int lane = threadIdx.x & 31;
    int n = blockIdx.x * 8 + (threadIdx.x >> 5);
    float acc = agg2[n * N_CLS + lane] + __ldg(b2 + lane);
    float m = acc;
#pragma unroll
    for (int o = 16; o; o >>= 1) m = fmaxf(m, __shfl_xor_sync(0xffffffffu, m, o));
    float p = __expf(acc - m);
#pragma unroll
    for (int o = 16; o; o >>= 1) p += __shfl_xor_sync(0xffffffffu, p, o);
    out[n * N_CLS + lane] = acc - m - __logf(p);
}

extern "C" void kernel_launch(void* const* d_in, const int* in_sizes, int n_in,
                              void* d_out, int out_size) {
    const float* x  = (const float*)d_in[0];
    const int*   ei = (const int*)d_in[1];   // int32 [2, E]
    const float* W1 = (const float*)d_in[2];
    const float* b1 = (const float*)d_in[3];
    const float* W2 = (const float*)d_in[4];
    const float* b2 = (const float*)d_in[5];
    float* out      = (float*)d_out;

    const int* src = ei;
    const int* dst = ei + N_EDGES;

    float* y;    cudaGetSymbolAddress((void**)&y,    g_y);
    float* agg1; cudaGetSymbolAddress((void**)&agg1, g_agg1);
    float* z;    cudaGetSymbolAddress((void**)&z,    g_z);
    float* agg2; cudaGetSymbolAddress((void**)&agg2, g_agg2);

    // 1. y = x @ W1  (also zeroes agg1/agg2)
    gemm_x_kernel<<<N_NODES / 50, 160>>>(x, W1, y);

    // 2. agg1[dst] += y[src]   (64 floats = 16 float4 per edge)
    scatter_kernel<4><<<N_EDGES * 16 / 256, 256>>>((const float4*)y, agg1, src, dst);

    // 3. z = relu(agg1 + b1) @ W2
    hidden_kernel<<<(N_NODES + 63) / 64, 256>>>(agg1, b1, W2, z);

    // 4. agg2[dst] += z[src]   (32 floats = 8 float4 per edge)
    scatter_kernel<3><<<N_EDGES * 8 / 256, 256>>>((const float4*)z, agg2, src, dst);

    // 5. out = log_softmax(agg2 + b2)
    lsm_kernel<<<N_NODES / 8, 256>>>(agg2, b2, out);
}